// round 1
// baseline (speedup 1.0000x reference)
#include <cuda_runtime.h>
#include <cstdint>

// Problem constants
#define B_   256
#define N_   133
#define D_   1024
#define H_   8
#define C_   128
#define MTOT (B_ * N_)        // 34048
#define NOUT 1024
#define NEG_SLOPE 0.2f

// ---------------- scratch (static device globals: no allocation) ----------
__device__ float g_buf[(size_t)MTOT * NOUT];   // g = x @ W.T  (139.5 MB)
__device__ float si_buf[MTOT * H_];            // si (uses attn_w[C:2C])
__device__ float sj_buf[MTOT * H_];            // sj (uses attn_w[0:C])

// ---------------- helpers -------------------------------------------------
__device__ __forceinline__ uint32_t cvt_tf32(float f) {
    uint32_t r;
    asm("cvt.rna.tf32.f32 %0, %1;" : "=r"(r) : "f"(f));
    return r;
}

__device__ __forceinline__ void mma_tf32(float* d, const uint32_t* a, const uint32_t* b) {
    asm volatile(
        "mma.sync.aligned.m16n8k8.row.col.f32.tf32.tf32.f32 "
        "{%0,%1,%2,%3}, {%4,%5,%6,%7}, {%8,%9}, {%0,%1,%2,%3};\n"
        : "+f"(d[0]), "+f"(d[1]), "+f"(d[2]), "+f"(d[3])
        : "r"(a[0]), "r"(a[1]), "r"(a[2]), "r"(a[3]),
          "r"(b[0]), "r"(b[1]));
}

#define CP_ASYNC16(dst_smem_u32, src_gmem) \
    asm volatile("cp.async.ca.shared.global [%0], [%1], 16;\n" \
                 :: "r"(dst_smem_u32), "l"(src_gmem))

// =========================================================================
// Kernel 1: g = x @ W.T    (tf32 mma.sync, 128x128 block tile, K-chunk 32)
// M = 34048 (266 tiles), N = 1024 (8 tiles), K = 1024 (32 chunks)
// =========================================================================
#define KC  32
#define PAD 36   // row pad (floats) -> conflict-free fragment LDS

__global__ __launch_bounds__(256)
void gemm1_kernel(const float* __restrict__ x, const float* __restrict__ W) {
    extern __shared__ float sm1[];
    float (*As)[128][PAD] = reinterpret_cast<float (*)[128][PAD]>(sm1);
    float (*Bs)[128][PAD] = reinterpret_cast<float (*)[128][PAD]>(sm1 + 2 * 128 * PAD);

    const int tid  = threadIdx.x;
    const int bn   = blockIdx.x;   // 0..7
    const int bm   = blockIdx.y;   // 0..265
    const int lane = tid & 31;
    const int warp = tid >> 5;
    const int wm   = warp & 3;     // 4 warps along M (32 rows each)
    const int wn   = warp >> 2;    // 2 warps along N (64 cols each)

    // per-thread load coords: 4 iterations, 32 rows x 8 float4 segs per iter
    const int lrow = tid >> 3;        // 0..31
    const int lc4  = (tid & 7) * 4;   // 0,4,...,28

    const float* xg = x + (size_t)(bm * 128) * D_ + lc4;
    const float* wg = W + (size_t)(bn * 128) * D_ + lc4;

    auto load_tiles = [&](int buf, int kc) {
#pragma unroll
        for (int it = 0; it < 4; it++) {
            int r = lrow + it * 32;
            uint32_t da = (uint32_t)__cvta_generic_to_shared(&As[buf][r][lc4]);
            CP_ASYNC16(da, xg + (size_t)r * D_ + kc);
            uint32_t db = (uint32_t)__cvta_generic_to_shared(&Bs[buf][r][lc4]);
            CP_ASYNC16(db, wg + (size_t)r * D_ + kc);
        }
        asm volatile("cp.async.commit_group;\n" ::: "memory");
    };

    float acc[2][8][4];
#pragma unroll
    for (int mt = 0; mt < 2; mt++)
#pragma unroll
        for (int nt = 0; nt < 8; nt++)
#pragma unroll
            for (int q = 0; q < 4; q++) acc[mt][nt][q] = 0.f;

    load_tiles(0, 0);

    const int r4 = lane >> 2;   // 0..7
    const int c4 = lane & 3;    // 0..3

    for (int kc = 0; kc < D_; kc += KC) {
        int buf = (kc / KC) & 1;
        if (kc + KC < D_) {
            load_tiles(buf ^ 1, kc + KC);
            asm volatile("cp.async.wait_group 1;\n" ::: "memory");
        } else {
            asm volatile("cp.async.wait_group 0;\n" ::: "memory");
        }
        __syncthreads();

#pragma unroll
        for (int kk = 0; kk < KC / 8; kk++) {
            const int k0 = kk * 8;
            uint32_t af[2][4];
            uint32_t bf[8][2];
#pragma unroll
            for (int mt = 0; mt < 2; mt++) {
                const int rb = wm * 32 + mt * 16;
                af[mt][0] = cvt_tf32(As[buf][rb + r4][k0 + c4]);
                af[mt][1] = cvt_tf32(As[buf][rb + r4 + 8][k0 + c4]);
                af[mt][2] = cvt_tf32(As[buf][rb + r4][k0 + c4 + 4]);
                af[mt][3] = cvt_tf32(As[buf][rb + r4 + 8][k0 + c4 + 4]);
            }
#pragma unroll
            for (int nt = 0; nt < 8; nt++) {
                const int nb = wn * 64 + nt * 8 + r4;
                bf[nt][0] = cvt_tf32(Bs[buf][nb][k0 + c4]);
                bf[nt][1] = cvt_tf32(Bs[buf][nb][k0 + c4 + 4]);
            }
#pragma unroll
            for (int mt = 0; mt < 2; mt++)
#pragma unroll
                for (int nt = 0; nt < 8; nt++)
                    mma_tf32(acc[mt][nt], af[mt], bf[nt]);
        }
        __syncthreads();
    }

    // epilogue: write g
    const int c2 = (lane & 3) * 2;
#pragma unroll
    for (int mt = 0; mt < 2; mt++) {
        const int m0 = bm * 128 + wm * 32 + mt * 16;
#pragma unroll
        for (int nt = 0; nt < 8; nt++) {
            const int n0 = bn * 128 + wn * 64 + nt * 8 + c2;
            float2 v0 = make_float2(acc[mt][nt][0], acc[mt][nt][1]);
            float2 v1 = make_float2(acc[mt][nt][2], acc[mt][nt][3]);
            *reinterpret_cast<float2*>(&g_buf[(size_t)(m0 + r4) * NOUT + n0])     = v0;
            *reinterpret_cast<float2*>(&g_buf[(size_t)(m0 + r4 + 8) * NOUT + n0]) = v1;
        }
    }
}

// =========================================================================
// Kernel 2: si/sj per (b,n,h):  sj = <g_row, attn_w[0:128]>, si = <g_row, attn_w[128:256]>
// one block per row m, one warp per head
// =========================================================================
__global__ __launch_bounds__(256)
void scores_kernel(const float* __restrict__ attn_w) {
    const int m    = blockIdx.x;           // 0..MTOT-1
    const int warp = threadIdx.x >> 5;     // head
    const int lane = threadIdx.x & 31;

    const float4 gv = reinterpret_cast<const float4*>(g_buf + (size_t)m * NOUT + warp * C_)[lane];
    const float4 wl = reinterpret_cast<const float4*>(attn_w)[lane];
    const float4 wr = reinterpret_cast<const float4*>(attn_w + C_)[lane];

    float s_j = gv.x * wl.x + gv.y * wl.y + gv.z * wl.z + gv.w * wl.w;
    float s_i = gv.x * wr.x + gv.y * wr.y + gv.z * wr.z + gv.w * wr.w;
#pragma unroll
    for (int off = 16; off > 0; off >>= 1) {
        s_j += __shfl_xor_sync(0xffffffffu, s_j, off);
        s_i += __shfl_xor_sync(0xffffffffu, s_i, off);
    }
    if (lane == 0) {
        sj_buf[m * H_ + warp] = s_j;
        si_buf[m * H_ + warp] = s_i;
    }
}

// =========================================================================
// Kernel 4 (fused): per (b,h) build P, column-softmax (over i!), out = P @ g
//   P[i][j] = adj[i][j] ? exp(lrelu(si[i]+sj[j])) : 0
//   denom[j] = sum_i P[i][j];  out[i,:] = sum_j (P[i][j]/denom[j]) * g[j,:]
// =========================================================================
#define PPAD 136

__global__ __launch_bounds__(256)
void attn_kernel(const float* __restrict__ adj, float* __restrict__ out) {
    extern __shared__ float sm4[];
    float* gsh = sm4;                        // 133*128
    float* Psh = gsh + N_ * C_;              // 133*PPAD
    float* ssi = Psh + N_ * PPAD;            // 133
    float* ssj = ssi + N_;                   // 133
    float* dsh = ssj + N_;                   // 133 (1/denom)

    const int h = blockIdx.x;
    const int b = blockIdx.y;
    const int tid = threadIdx.x;

    for (int i = tid; i < N_; i += 256) {
        ssi[i] = si_buf[((size_t)b * N_ + i) * H_ + h];
        ssj[i] = sj_buf[((size_t)b * N_ + i) * H_ + h];
    }
    // stage g slice [133][128]
    for (int p = tid; p < N_ * (C_ / 4); p += 256) {
        int j  = p / (C_ / 4);
        int f4 = p % (C_ / 4);
        reinterpret_cast<float4*>(gsh)[p] =
            reinterpret_cast<const float4*>(g_buf + ((size_t)(b * N_ + j) * H_ + h) * C_)[f4];
    }
    __syncthreads();

    // build unnormalized P
    for (int p = tid; p < N_ * N_; p += 256) {
        int i = p / N_;
        int j = p - i * N_;
        float a = adj[p];
        float v = ssi[i] + ssj[j];
        v = (v > 0.f) ? v : NEG_SLOPE * v;
        Psh[i * PPAD + j] = (a != 0.f) ? __expf(v) : 0.f;
    }
    __syncthreads();

    // column sums over i -> inverse denominators
    for (int j = tid; j < N_; j += 256) {
        float s = 0.f;
        for (int i = 0; i < N_; i++) s += Psh[i * PPAD + j];
        dsh[j] = 1.0f / s;
    }
    __syncthreads();

    // pre-scale g rows by 1/denom[j]  (fold softmax normalization into g)
    for (int p = tid; p < N_ * (C_ / 4); p += 256) {
        int j = p / (C_ / 4);
        float iv = dsh[j];
        float4 v = reinterpret_cast<float4*>(gsh)[p];
        v.x *= iv; v.y *= iv; v.z *= iv; v.w *= iv;
        reinterpret_cast<float4*>(gsh)[p] = v;
    }
    __syncthreads();

    // out[i,:] = sum_j P[i][j] * gsh[j,:]   (warp per row, lanes over f)
    const int warp = tid >> 5;
    const int lane = tid & 31;
    const float4* g4 = reinterpret_cast<const float4*>(gsh);
    for (int i = warp; i < N_; i += 8) {
        const float* Prow = Psh + i * PPAD;
        float4 acc = make_float4(0.f, 0.f, 0.f, 0.f);
#pragma unroll 4
        for (int j = 0; j < N_; j++) {
            float pv = Prow[j];
            float4 gv = g4[j * (C_ / 4) + lane];
            acc.x += pv * gv.x;
            acc.y += pv * gv.y;
            acc.z += pv * gv.z;
            acc.w += pv * gv.w;
        }
        reinterpret_cast<float4*>(out + (size_t)(b * N_ + i) * NOUT + h * C_)[lane] = acc;
    }
}

// =========================================================================
// launch
// =========================================================================
extern "C" void kernel_launch(void* const* d_in, const int* in_sizes, int n_in,
                              void* d_out, int out_size) {
    const float* x      = (const float*)d_in[0];
    const float* W      = (const float*)d_in[1];
    const float* attn_w = (const float*)d_in[2];
    const float* adj    = (const float*)d_in[3];
    float* out          = (float*)d_out;

    const int smem1 = 2 * 128 * PAD * 2 * sizeof(float);                     // 73728 B
    const int smem4 = (N_ * C_ + N_ * PPAD + 3 * N_) * sizeof(float);        // ~142 KB

    cudaFuncSetAttribute(gemm1_kernel, cudaFuncAttributeMaxDynamicSharedMemorySize, smem1);
    cudaFuncSetAttribute(attn_kernel,  cudaFuncAttributeMaxDynamicSharedMemorySize, smem4);

    dim3 g1(NOUT / 128, MTOT / 128);   // (8, 266)
    gemm1_kernel<<<g1, 256, smem1>>>(x, W);

    scores_kernel<<<MTOT, 256>>>(attn_w);

    dim3 g4(H_, B_);                    // (8, 256)
    attn_kernel<<<g4, 256, smem4>>>(adj, out);
}

// round 2
// speedup vs baseline: 1.0010x; 1.0010x over previous
#include <cuda_runtime.h>
#include <cstdint>

// Problem constants
#define B_   256
#define N_   133
#define D_   1024
#define H_   8
#define C_   128
#define MTOT (B_ * N_)        // 34048
#define NOUT 1024
#define NEG_SLOPE 0.2f

// ---------------- scratch (static device globals: no allocation) ----------
__device__ float g_buf[(size_t)MTOT * NOUT];   // g = x @ W.T  (139.5 MB)
__device__ float si_buf[MTOT * H_];
__device__ float sj_buf[MTOT * H_];

// ---------------- helpers -------------------------------------------------
__device__ __forceinline__ uint32_t cvt_tf32(float f) {
    uint32_t r;
    asm("cvt.rna.tf32.f32 %0, %1;" : "=r"(r) : "f"(f));
    return r;
}

__device__ __forceinline__ void mma_tf32(float* d, const uint32_t* a, const uint32_t* b) {
    asm volatile(
        "mma.sync.aligned.m16n8k8.row.col.f32.tf32.tf32.f32 "
        "{%0,%1,%2,%3}, {%4,%5,%6,%7}, {%8,%9}, {%0,%1,%2,%3};\n"
        : "+f"(d[0]), "+f"(d[1]), "+f"(d[2]), "+f"(d[3])
        : "r"(a[0]), "r"(a[1]), "r"(a[2]), "r"(a[3]),
          "r"(b[0]), "r"(b[1]));
}

#define CP_ASYNC16(dst_smem_u32, src_gmem) \
    asm volatile("cp.async.ca.shared.global [%0], [%1], 16;\n" \
                 :: "r"(dst_smem_u32), "l"(src_gmem))

// =========================================================================
// Kernel 1: g = x @ W.T    (tf32 mma.sync, 128x128 block tile, K-chunk 32)
// =========================================================================
#define KC  32
#define PAD 36

__global__ __launch_bounds__(256)
void gemm1_kernel(const float* __restrict__ x, const float* __restrict__ W) {
    extern __shared__ float sm1[];
    float (*As)[128][PAD] = reinterpret_cast<float (*)[128][PAD]>(sm1);
    float (*Bs)[128][PAD] = reinterpret_cast<float (*)[128][PAD]>(sm1 + 2 * 128 * PAD);

    const int tid  = threadIdx.x;
    const int bn   = blockIdx.x;
    const int bm   = blockIdx.y;
    const int lane = tid & 31;
    const int warp = tid >> 5;
    const int wm   = warp & 3;
    const int wn   = warp >> 2;

    const int lrow = tid >> 3;
    const int lc4  = (tid & 7) * 4;

    const float* xg = x + (size_t)(bm * 128) * D_ + lc4;
    const float* wg = W + (size_t)(bn * 128) * D_ + lc4;

    auto load_tiles = [&](int buf, int kc) {
#pragma unroll
        for (int it = 0; it < 4; it++) {
            int r = lrow + it * 32;
            uint32_t da = (uint32_t)__cvta_generic_to_shared(&As[buf][r][lc4]);
            CP_ASYNC16(da, xg + (size_t)r * D_ + kc);
            uint32_t db = (uint32_t)__cvta_generic_to_shared(&Bs[buf][r][lc4]);
            CP_ASYNC16(db, wg + (size_t)r * D_ + kc);
        }
        asm volatile("cp.async.commit_group;\n" ::: "memory");
    };

    float acc[2][8][4];
#pragma unroll
    for (int mt = 0; mt < 2; mt++)
#pragma unroll
        for (int nt = 0; nt < 8; nt++)
#pragma unroll
            for (int q = 0; q < 4; q++) acc[mt][nt][q] = 0.f;

    load_tiles(0, 0);

    const int r4 = lane >> 2;
    const int c4 = lane & 3;

    for (int kc = 0; kc < D_; kc += KC) {
        int buf = (kc / KC) & 1;
        if (kc + KC < D_) {
            load_tiles(buf ^ 1, kc + KC);
            asm volatile("cp.async.wait_group 1;\n" ::: "memory");
        } else {
            asm volatile("cp.async.wait_group 0;\n" ::: "memory");
        }
        __syncthreads();

#pragma unroll
        for (int kk = 0; kk < KC / 8; kk++) {
            const int k0 = kk * 8;
            uint32_t af[2][4];
            uint32_t bf[8][2];
#pragma unroll
            for (int mt = 0; mt < 2; mt++) {
                const int rb = wm * 32 + mt * 16;
                af[mt][0] = cvt_tf32(As[buf][rb + r4][k0 + c4]);
                af[mt][1] = cvt_tf32(As[buf][rb + r4 + 8][k0 + c4]);
                af[mt][2] = cvt_tf32(As[buf][rb + r4][k0 + c4 + 4]);
                af[mt][3] = cvt_tf32(As[buf][rb + r4 + 8][k0 + c4 + 4]);
            }
#pragma unroll
            for (int nt = 0; nt < 8; nt++) {
                const int nb = wn * 64 + nt * 8 + r4;
                bf[nt][0] = cvt_tf32(Bs[buf][nb][k0 + c4]);
                bf[nt][1] = cvt_tf32(Bs[buf][nb][k0 + c4 + 4]);
            }
#pragma unroll
            for (int mt = 0; mt < 2; mt++)
#pragma unroll
                for (int nt = 0; nt < 8; nt++)
                    mma_tf32(acc[mt][nt], af[mt], bf[nt]);
        }
        __syncthreads();
    }

    const int c2 = (lane & 3) * 2;
#pragma unroll
    for (int mt = 0; mt < 2; mt++) {
        const int m0 = bm * 128 + wm * 32 + mt * 16;
#pragma unroll
        for (int nt = 0; nt < 8; nt++) {
            const int n0 = bn * 128 + wn * 64 + nt * 8 + c2;
            float2 v0 = make_float2(acc[mt][nt][0], acc[mt][nt][1]);
            float2 v1 = make_float2(acc[mt][nt][2], acc[mt][nt][3]);
            *reinterpret_cast<float2*>(&g_buf[(size_t)(m0 + r4) * NOUT + n0])     = v0;
            *reinterpret_cast<float2*>(&g_buf[(size_t)(m0 + r4 + 8) * NOUT + n0]) = v1;
        }
    }
}

// =========================================================================
// Kernel 2: si/sj
// =========================================================================
__global__ __launch_bounds__(256)
void scores_kernel(const float* __restrict__ attn_w) {
    const int m    = blockIdx.x;
    const int warp = threadIdx.x >> 5;
    const int lane = threadIdx.x & 31;

    const float4 gv = reinterpret_cast<const float4*>(g_buf + (size_t)m * NOUT + warp * C_)[lane];
    const float4 wl = reinterpret_cast<const float4*>(attn_w)[lane];
    const float4 wr = reinterpret_cast<const float4*>(attn_w + C_)[lane];

    float s_j = gv.x * wl.x + gv.y * wl.y + gv.z * wl.z + gv.w * wl.w;
    float s_i = gv.x * wr.x + gv.y * wr.y + gv.z * wr.z + gv.w * wr.w;
#pragma unroll
    for (int off = 16; off > 0; off >>= 1) {
        s_j += __shfl_xor_sync(0xffffffffu, s_j, off);
        s_i += __shfl_xor_sync(0xffffffffu, s_i, off);
    }
    if (lane == 0) {
        sj_buf[m * H_ + warp] = s_j;
        si_buf[m * H_ + warp] = s_i;
    }
}

// =========================================================================
// Kernel 3 (tensor-core attention): per (b,h)
//   P[i][j] = adj[i][j] ? exp(lrelu(si[i]+sj[j])) : 0        (in shared)
//   dinv[j] = 1 / sum_i P[i][j]                              (softmax axis=1)
//   gT[f][j] = g[b,j,h,f] * dinv[j]                          (col-major B)
//   out[b,i,h,:] = mma( P, gT )                              (tf32 mma.sync)
// M=144 (pad), N=128, K=136 (pad, zero)
// =========================================================================
#define PST 140   // row stride for Psh and gT (140 mod 32 = 12 -> conflict-free frags)
#define AKS 17    // K-steps (17*8 = 136 >= 133)

__global__ __launch_bounds__(256)
void attn_mma_kernel(const float* __restrict__ adj, float* __restrict__ out) {
    extern __shared__ float sm[];
    float* Psh  = sm;                    // [144][PST]
    float* gT   = Psh + 144 * PST;       // [128][PST]
    float* ssi  = gT  + 128 * PST;       // [144]
    float* ssj  = ssi + 144;             // [144]
    float* dinv = ssj + 144;             // [144]

    const int h = blockIdx.x;
    const int b = blockIdx.y;
    const int tid  = threadIdx.x;
    const int lane = tid & 31;
    const int warp = tid >> 5;

    // zero P and gT (covers all pad rows/cols)
    for (int p = tid; p < (144 + 128) * PST; p += 256) sm[p] = 0.f;
    for (int i = tid; i < N_; i += 256) {
        ssi[i] = si_buf[((size_t)b * N_ + i) * H_ + h];
        ssj[i] = sj_buf[((size_t)b * N_ + i) * H_ + h];
    }
    __syncthreads();

    // build unnormalized P (warp per row group, lanes over j)
    for (int i = warp; i < N_; i += 8) {
        const float siv = ssi[i];
        const float* arow = adj + i * N_;
        for (int j = lane; j < N_; j += 32) {
            float v = siv + ssj[j];
            v = (v > 0.f) ? v : NEG_SLOPE * v;
            Psh[i * PST + j] = (arow[j] != 0.f) ? __expf(v) : 0.f;
        }
    }

    // transpose-stage g: gT[f][j] = g[b,j,h,f]
    for (int j = warp; j < N_; j += 8) {
        const float* gr = g_buf + ((size_t)(b * N_ + j) * H_ + h) * C_;
        for (int f = lane; f < C_; f += 32)
            gT[f * PST + j] = gr[f];
    }
    __syncthreads();

    // column sums over i -> 1/denom
    for (int j = tid; j < N_; j += 256) {
        float s = 0.f;
        for (int i = 0; i < N_; i++) s += Psh[i * PST + j];
        dinv[j] = 1.0f / s;
    }
    __syncthreads();

    // fold 1/denom into gT columns
    for (int f = warp; f < C_; f += 8)
        for (int j = lane; j < N_; j += 32)
            gT[f * PST + j] *= dinv[j];
    __syncthreads();

    // mma: out = P @ gT^T ; warp layout: wm in 0..3 over M-tiles {wm, wm+4, wm+8},
    // wn in 0..1 over 64-col halves (8 n8 tiles each)
    const int wm = warp & 3;
    const int wn = warp >> 2;
    const int r4 = lane >> 2;
    const int c4 = lane & 3;

    float acc[3][8][4];
#pragma unroll
    for (int mi = 0; mi < 3; mi++)
#pragma unroll
        for (int nt = 0; nt < 8; nt++)
#pragma unroll
            for (int q = 0; q < 4; q++) acc[mi][nt][q] = 0.f;

    for (int ks = 0; ks < AKS; ks++) {
        const int k0 = ks * 8;
        uint32_t bf[8][2];
#pragma unroll
        for (int nt = 0; nt < 8; nt++) {
            const int n = wn * 64 + nt * 8 + r4;
            bf[nt][0] = cvt_tf32(gT[n * PST + k0 + c4]);
            bf[nt][1] = cvt_tf32(gT[n * PST + k0 + c4 + 4]);
        }
#pragma unroll
        for (int mi = 0; mi < 3; mi++) {
            const int mt = wm + mi * 4;
            if (mt >= 9) break;
            const int m0 = mt * 16;
            uint32_t af[4];
            af[0] = cvt_tf32(Psh[(m0 + r4) * PST + k0 + c4]);
            af[1] = cvt_tf32(Psh[(m0 + r4 + 8) * PST + k0 + c4]);
            af[2] = cvt_tf32(Psh[(m0 + r4) * PST + k0 + c4 + 4]);
            af[3] = cvt_tf32(Psh[(m0 + r4 + 8) * PST + k0 + c4 + 4]);
#pragma unroll
            for (int nt = 0; nt < 8; nt++)
                mma_tf32(acc[mi][nt], af, bf[nt]);
        }
    }

    // epilogue: out[b, i, h*C + f]
    const int c2 = c4 * 2;
#pragma unroll
    for (int mi = 0; mi < 3; mi++) {
        const int mt = wm + mi * 4;
        if (mt >= 9) break;
        const int i1 = mt * 16 + r4;
        const int i2 = i1 + 8;
#pragma unroll
        for (int nt = 0; nt < 8; nt++) {
            const int f0 = wn * 64 + nt * 8 + c2;
            if (i1 < N_) {
                float2 v = make_float2(acc[mi][nt][0], acc[mi][nt][1]);
                *reinterpret_cast<float2*>(out + (size_t)(b * N_ + i1) * NOUT + h * C_ + f0) = v;
            }
            if (i2 < N_) {
                float2 v = make_float2(acc[mi][nt][2], acc[mi][nt][3]);
                *reinterpret_cast<float2*>(out + (size_t)(b * N_ + i2) * NOUT + h * C_ + f0) = v;
            }
        }
    }
}

// =========================================================================
// launch
// =========================================================================
extern "C" void kernel_launch(void* const* d_in, const int* in_sizes, int n_in,
                              void* d_out, int out_size) {
    const float* x      = (const float*)d_in[0];
    const float* W      = (const float*)d_in[1];
    const float* attn_w = (const float*)d_in[2];
    const float* adj    = (const float*)d_in[3];
    float* out          = (float*)d_out;

    const int smem1 = 2 * 128 * PAD * 2 * sizeof(float);
    const int smem3 = ((144 + 128) * PST + 3 * 144) * sizeof(float);   // ~154 KB

    cudaFuncSetAttribute(gemm1_kernel,    cudaFuncAttributeMaxDynamicSharedMemorySize, smem1);
    cudaFuncSetAttribute(attn_mma_kernel, cudaFuncAttributeMaxDynamicSharedMemorySize, smem3);

    dim3 g1(NOUT / 128, MTOT / 128);
    gemm1_kernel<<<g1, 256, smem1>>>(x, W);

    scores_kernel<<<MTOT, 256>>>(attn_w);

    dim3 g3(H_, B_);
    attn_mma_kernel<<<g3, 256, smem3>>>(adj, out);
}

// round 3
// speedup vs baseline: 1.7551x; 1.7534x over previous
#include <cuda_runtime.h>
#include <cstdint>

// Problem constants
#define B_   256
#define N_   133
#define D_   1024
#define H_   8
#define C_   128
#define MTOT (B_ * N_)        // 34048
#define NOUT 1024
#define NEG_SLOPE 0.2f

#define GTS 136               // gT row stride in floats (16B multiple)
#define PST 137               // P row stride (odd -> conflict-free A-frag LDS)

// ---------------- scratch (static device globals: no allocation) ----------
// gT_buf[b][h][f][j] : transposed g, rows padded to GTS (cols 133..135 stay 0)
__device__ float gT_buf[(size_t)B_ * H_ * C_ * GTS];   // ~142.6 MB
__device__ float si_buf[H_ * MTOT];                    // [h][m]
__device__ float sj_buf[H_ * MTOT];

// ---------------- helpers -------------------------------------------------
__device__ __forceinline__ uint32_t cvt_tf32(float f) {
    uint32_t r;
    asm("cvt.rna.tf32.f32 %0, %1;" : "=r"(r) : "f"(f));
    return r;
}

__device__ __forceinline__ void mma_tf32(float* d, const uint32_t* a, const uint32_t* b) {
    asm volatile(
        "mma.sync.aligned.m16n8k8.row.col.f32.tf32.tf32.f32 "
        "{%0,%1,%2,%3}, {%4,%5,%6,%7}, {%8,%9}, {%0,%1,%2,%3};\n"
        : "+f"(d[0]), "+f"(d[1]), "+f"(d[2]), "+f"(d[3])
        : "r"(a[0]), "r"(a[1]), "r"(a[2]), "r"(a[3]),
          "r"(b[0]), "r"(b[1]));
}

#define CP_ASYNC16(dst_smem_u32, src_gmem) \
    asm volatile("cp.async.ca.shared.global [%0], [%1], 16;\n" \
                 :: "r"(dst_smem_u32), "l"(src_gmem))

// =========================================================================
// Kernel 1: g = x @ W.T  (tf32 mma), fused epilogue:
//   - si/sj scores for this (128-row, head=bn) tile
//   - transposed write to gT_buf[b][h][f][j]
// =========================================================================
#define KC  32
#define PAD 36
#define EST 133   // epilogue smem tile stride (odd -> conflict-free transpose)

__global__ __launch_bounds__(256)
void gemm1_kernel(const float* __restrict__ x, const float* __restrict__ W,
                  const float* __restrict__ attn_w) {
    extern __shared__ float sm1[];
    float (*As)[128][PAD] = reinterpret_cast<float (*)[128][PAD]>(sm1);
    float (*Bs)[128][PAD] = reinterpret_cast<float (*)[128][PAD]>(sm1 + 2 * 128 * PAD);

    const int tid  = threadIdx.x;
    const int bn   = blockIdx.x;   // head
    const int bm   = blockIdx.y;
    const int lane = tid & 31;
    const int warp = tid >> 5;
    const int wm   = warp & 3;
    const int wn   = warp >> 2;

    const int lrow = tid >> 3;
    const int lc4  = (tid & 7) * 4;

    const float* xg = x + (size_t)(bm * 128) * D_ + lc4;
    const float* wg = W + (size_t)(bn * 128) * D_ + lc4;

    auto load_tiles = [&](int buf, int kc) {
#pragma unroll
        for (int it = 0; it < 4; it++) {
            int r = lrow + it * 32;
            uint32_t da = (uint32_t)__cvta_generic_to_shared(&As[buf][r][lc4]);
            CP_ASYNC16(da, xg + (size_t)r * D_ + kc);
            uint32_t db = (uint32_t)__cvta_generic_to_shared(&Bs[buf][r][lc4]);
            CP_ASYNC16(db, wg + (size_t)r * D_ + kc);
        }
        asm volatile("cp.async.commit_group;\n" ::: "memory");
    };

    float acc[2][8][4];
#pragma unroll
    for (int mt = 0; mt < 2; mt++)
#pragma unroll
        for (int nt = 0; nt < 8; nt++)
#pragma unroll
            for (int q = 0; q < 4; q++) acc[mt][nt][q] = 0.f;

    load_tiles(0, 0);

    const int r4 = lane >> 2;
    const int c4 = lane & 3;

    for (int kc = 0; kc < D_; kc += KC) {
        int buf = (kc / KC) & 1;
        if (kc + KC < D_) {
            load_tiles(buf ^ 1, kc + KC);
            asm volatile("cp.async.wait_group 1;\n" ::: "memory");
        } else {
            asm volatile("cp.async.wait_group 0;\n" ::: "memory");
        }
        __syncthreads();

#pragma unroll
        for (int kk = 0; kk < KC / 8; kk++) {
            const int k0 = kk * 8;
            uint32_t af[2][4];
            uint32_t bf[8][2];
#pragma unroll
            for (int mt = 0; mt < 2; mt++) {
                const int rb = wm * 32 + mt * 16;
                af[mt][0] = cvt_tf32(As[buf][rb + r4][k0 + c4]);
                af[mt][1] = cvt_tf32(As[buf][rb + r4 + 8][k0 + c4]);
                af[mt][2] = cvt_tf32(As[buf][rb + r4][k0 + c4 + 4]);
                af[mt][3] = cvt_tf32(As[buf][rb + r4 + 8][k0 + c4 + 4]);
            }
#pragma unroll
            for (int nt = 0; nt < 8; nt++) {
                const int nb = wn * 64 + nt * 8 + r4;
                bf[nt][0] = cvt_tf32(Bs[buf][nb][k0 + c4]);
                bf[nt][1] = cvt_tf32(Bs[buf][nb][k0 + c4 + 4]);
            }
#pragma unroll
            for (int mt = 0; mt < 2; mt++)
#pragma unroll
                for (int nt = 0; nt < 8; nt++)
                    mma_tf32(acc[mt][nt], af[mt], bf[nt]);
        }
        __syncthreads();
    }

    // ---------------- fused epilogue ----------------
    // stage the 128x128 tile in smem (reuse As/Bs region), stride EST (odd)
    float* Es = sm1;   // [128][EST]
    const int c2 = (lane & 3) * 2;
#pragma unroll
    for (int mt = 0; mt < 2; mt++) {
        const int rA = wm * 32 + mt * 16 + r4;
#pragma unroll
        for (int nt = 0; nt < 8; nt++) {
            const int n0 = wn * 64 + nt * 8 + c2;
            Es[rA * EST + n0]           = acc[mt][nt][0];
            Es[rA * EST + n0 + 1]       = acc[mt][nt][1];
            Es[(rA + 8) * EST + n0]     = acc[mt][nt][2];
            Es[(rA + 8) * EST + n0 + 1] = acc[mt][nt][3];
        }
    }
    __syncthreads();

    // si/sj for 16 rows per warp
    {
        const float4 wl4 = reinterpret_cast<const float4*>(attn_w)[lane];
        const float4 wr4 = reinterpret_cast<const float4*>(attn_w + C_)[lane];
#pragma unroll
        for (int rr = 0; rr < 16; rr++) {
            const int r = warp * 16 + rr;
            const float* er = Es + r * EST + lane * 4;
            float a0 = er[0], a1 = er[1], a2 = er[2], a3 = er[3];
            float pj = a0 * wl4.x + a1 * wl4.y + a2 * wl4.z + a3 * wl4.w;
            float pi = a0 * wr4.x + a1 * wr4.y + a2 * wr4.z + a3 * wr4.w;
#pragma unroll
            for (int off = 16; off > 0; off >>= 1) {
                pj += __shfl_xor_sync(0xffffffffu, pj, off);
                pi += __shfl_xor_sync(0xffffffffu, pi, off);
            }
            if (lane == 0) {
                const int mg = bm * 128 + r;
                sj_buf[bn * MTOT + mg] = pj;
                si_buf[bn * MTOT + mg] = pi;
            }
        }
    }

    // transposed write: gT_buf[(b*8+h)*128 + f][n], h = bn
#pragma unroll
    for (int ff = 0; ff < 16; ff++) {
        const int f = warp * 16 + ff;
#pragma unroll
        for (int c = 0; c < 4; c++) {
            const int ml = c * 32 + lane;
            const float v = Es[ml * EST + f];
            const int mg = bm * 128 + ml;
            const int bb = mg / 133;
            const int nn = mg - bb * 133;
            gT_buf[((size_t)(bb * H_ + bn) * C_ + f) * GTS + nn] = v;
        }
    }
}

// =========================================================================
// Kernel 2 (attention): per (b,h)
//   P[i][j] = adj ? exp(lrelu(si[i]+sj[j])) : 0
//   dinv[j] = 1/sum_i P[i][j]  -> fold into P columns
//   out = P @ g  via tf32 mma; B-frags from cp.async-staged swizzled gT
// =========================================================================
#define AKS 17    // K-steps (136)

__global__ __launch_bounds__(256)
void attn_mma_kernel(const float* __restrict__ adj, float* __restrict__ out) {
    extern __shared__ float sm[];
    float* Psh  = sm;                    // [144][PST]
    float* gTs  = Psh + 144 * PST;       // [128][GTS], 16B-column XOR swizzle
    float* ssi  = gTs + 128 * GTS;       // [144]
    float* ssj  = ssi + 144;
    float* dinv = ssj + 144;

    const int h = blockIdx.x;
    const int b = blockIdx.y;
    const int tid  = threadIdx.x;
    const int lane = tid & 31;
    const int warp = tid >> 5;

    // 1) stage gT slice via cp.async (128 rows x 34 float4), swizzled
    {
        const float* gsrc = gT_buf + (size_t)(b * H_ + h) * C_ * GTS;
#pragma unroll
        for (int it = 0; it < 17; it++) {
            const int p  = tid + it * 256;   // 0..4351
            const int f  = p / 34;
            const int j4 = p - f * 34;
            const int sw = (j4 < 32) ? (j4 ^ ((f >> 3) & 7)) : j4;
            uint32_t dst = (uint32_t)__cvta_generic_to_shared(&gTs[f * GTS + sw * 4]);
            CP_ASYNC16(dst, gsrc + f * GTS + j4 * 4);
        }
        asm volatile("cp.async.commit_group;\n" ::: "memory");
    }

    // 2) scores to smem + zero P
    for (int i = tid; i < 144; i += 256) {
        ssi[i] = (i < N_) ? si_buf[h * MTOT + b * N_ + i] : 0.f;
        ssj[i] = (i < N_) ? sj_buf[h * MTOT + b * N_ + i] : 0.f;
    }
    for (int p = tid; p < 144 * PST; p += 256) Psh[p] = 0.f;
    __syncthreads();

    // 3) build unnormalized P
    for (int p = tid; p < N_ * N_; p += 256) {
        const int i = p / N_;
        const int j = p - i * N_;
        float v = ssi[i] + ssj[j];
        v = (v > 0.f) ? v : NEG_SLOPE * v;
        Psh[i * PST + j] = (adj[p] != 0.f) ? __expf(v) : 0.f;
    }
    __syncthreads();

    // 4) column sums (softmax axis = i) -> 1/denom
    for (int j = tid; j < N_; j += 256) {
        float s = 0.f;
#pragma unroll 7
        for (int i = 0; i < N_; i++) s += Psh[i * PST + j];
        dinv[j] = 1.0f / s;
    }
    __syncthreads();

    // 5) fold 1/denom into P columns
    for (int p = tid; p < N_ * PST; p += 256) {
        const int j = p % PST;
        if (j < N_) Psh[p] *= dinv[j];
    }

    asm volatile("cp.async.wait_group 0;\n" ::: "memory");
    __syncthreads();

    // 6) mma: out = P' @ gT^T
    const int wm = warp & 3;
    const int wn = warp >> 2;
    const int r4 = lane >> 2;
    const int c4 = lane & 3;

    float acc[3][8][4];
#pragma unroll
    for (int mi = 0; mi < 3; mi++)
#pragma unroll
        for (int nt = 0; nt < 8; nt++)
#pragma unroll
            for (int q = 0; q < 4; q++) acc[mi][nt][q] = 0.f;

#pragma unroll
    for (int ks = 0; ks < AKS; ks++) {
        const int k0  = ks * 8;
        const int ka  = k0 + c4;           // j4 = 2*ks
        const int kb  = ka + 4;            // j4 = 2*ks+1
        const int j4a = 2 * ks;
        const int j4b = 2 * ks + 1;
        uint32_t bf[8][2];
#pragma unroll
        for (int nt = 0; nt < 8; nt++) {
            const int n   = wn * 64 + nt * 8 + r4;
            const int key = (n >> 3) & 7;
            const int sa  = (j4a < 32) ? (j4a ^ key) : j4a;
            const int sb  = (j4b < 32) ? (j4b ^ key) : j4b;
            bf[nt][0] = cvt_tf32(gTs[n * GTS + sa * 4 + (ka & 3)]);
            bf[nt][1] = cvt_tf32(gTs[n * GTS + sb * 4 + (kb & 3)]);
        }
#pragma unroll
        for (int mi = 0; mi < 3; mi++) {
            const int mt = wm + mi * 4;
            if (mt >= 9) break;
            const int m0 = mt * 16;
            uint32_t af[4];
            af[0] = cvt_tf32(Psh[(m0 + r4) * PST + ka]);
            af[1] = cvt_tf32(Psh[(m0 + r4 + 8) * PST + ka]);
            af[2] = cvt_tf32(Psh[(m0 + r4) * PST + kb]);
            af[3] = cvt_tf32(Psh[(m0 + r4 + 8) * PST + kb]);
#pragma unroll
            for (int nt = 0; nt < 8; nt++)
                mma_tf32(acc[mi][nt], af, bf[nt]);
        }
    }

    // 7) epilogue
    const int c2 = c4 * 2;
#pragma unroll
    for (int mi = 0; mi < 3; mi++) {
        const int mt = wm + mi * 4;
        if (mt >= 9) break;
        const int i1 = mt * 16 + r4;
        const int i2 = i1 + 8;
#pragma unroll
        for (int nt = 0; nt < 8; nt++) {
            const int f0 = wn * 64 + nt * 8 + c2;
            if (i1 < N_) {
                float2 v = make_float2(acc[mi][nt][0], acc[mi][nt][1]);
                *reinterpret_cast<float2*>(out + (size_t)(b * N_ + i1) * NOUT + h * C_ + f0) = v;
            }
            if (i2 < N_) {
                float2 v = make_float2(acc[mi][nt][2], acc[mi][nt][3]);
                *reinterpret_cast<float2*>(out + (size_t)(b * N_ + i2) * NOUT + h * C_ + f0) = v;
            }
        }
    }
}

// =========================================================================
// launch
// =========================================================================
extern "C" void kernel_launch(void* const* d_in, const int* in_sizes, int n_in,
                              void* d_out, int out_size) {
    const float* x      = (const float*)d_in[0];
    const float* W      = (const float*)d_in[1];
    const float* attn_w = (const float*)d_in[2];
    const float* adj    = (const float*)d_in[3];
    float* out          = (float*)d_out;

    const int smem1 = 2 * 128 * PAD * 2 * sizeof(float);                       // 73728 B
    const int smem3 = (144 * PST + 128 * GTS + 3 * 144) * sizeof(float);       // ~150 KB

    cudaFuncSetAttribute(gemm1_kernel,    cudaFuncAttributeMaxDynamicSharedMemorySize, smem1);
    cudaFuncSetAttribute(attn_mma_kernel, cudaFuncAttributeMaxDynamicSharedMemorySize, smem3);

    dim3 g1(NOUT / 128, MTOT / 128);   // (8 heads, 266 row tiles)
    gemm1_kernel<<<g1, 256, smem1>>>(x, W, attn_w);

    dim3 g3(H_, B_);                   // (8, 256)
    attn_mma_kernel<<<g3, 256, smem3>>>(adj, out);
}

// round 4
// speedup vs baseline: 2.0658x; 1.1771x over previous
#include <cuda_runtime.h>
#include <cstdint>

// Problem constants
#define B_   256
#define N_   133
#define D_   1024
#define H_   8
#define C_   128
#define MTOT (B_ * N_)        // 34048
#define NOUT 1024
#define NEG_SLOPE 0.2f

#define GTS 136               // gT row stride in floats (16B multiple)
#define PST 140               // P row stride (mult of 4, conflict-free A-frags)

// ---------------- scratch (static device globals: no allocation) ----------
__device__ float gT_buf[(size_t)B_ * H_ * C_ * GTS];   // pre-cvt tf32 bits
__device__ float si_buf[H_ * MTOT];                    // [h][m]
__device__ float sj_buf[H_ * MTOT];
__device__ int   nz_cnt;
__device__ int   nz_list[N_ * N_];                     // packed (i<<8)|j

// ---------------- helpers -------------------------------------------------
__device__ __forceinline__ uint32_t cvt_tf32(float f) {
    uint32_t r;
    asm("cvt.rna.tf32.f32 %0, %1;" : "=r"(r) : "f"(f));
    return r;
}

__device__ __forceinline__ void mma_tf32(float* d, const uint32_t* a, const uint32_t* b) {
    asm volatile(
        "mma.sync.aligned.m16n8k8.row.col.f32.tf32.tf32.f32 "
        "{%0,%1,%2,%3}, {%4,%5,%6,%7}, {%8,%9}, {%0,%1,%2,%3};\n"
        : "+f"(d[0]), "+f"(d[1]), "+f"(d[2]), "+f"(d[3])
        : "r"(a[0]), "r"(a[1]), "r"(a[2]), "r"(a[3]),
          "r"(b[0]), "r"(b[1]));
}

#define CP_ASYNC16(dst_smem_u32, src_gmem) \
    asm volatile("cp.async.ca.shared.global [%0], [%1], 16;\n" \
                 :: "r"(dst_smem_u32), "l"(src_gmem))

// =========================================================================
// adjacency nonzero list (adj is shared by ALL (b,h) pairs)
// =========================================================================
__global__ void nz_zero_kernel() { nz_cnt = 0; }

__global__ __launch_bounds__(256)
void nz_build_kernel(const float* __restrict__ adj) {
    const int p = blockIdx.x * 256 + threadIdx.x;
    if (p < N_ * N_ && adj[p] != 0.f) {
        const int i = p / N_;
        const int j = p - i * N_;
        const int k = atomicAdd(&nz_cnt, 1);
        nz_list[k] = (i << 8) | j;
    }
}

// =========================================================================
// Kernel 1: g = x @ W.T  (tf32 mma) + fused epilogue (si/sj + transposed,
// tf32-pre-rounded gT write)
// =========================================================================
#define KC  32
#define PAD 36
#define EST 133

__global__ __launch_bounds__(256)
void gemm1_kernel(const float* __restrict__ x, const float* __restrict__ W,
                  const float* __restrict__ attn_w) {
    extern __shared__ float sm1[];
    float (*As)[128][PAD] = reinterpret_cast<float (*)[128][PAD]>(sm1);
    float (*Bs)[128][PAD] = reinterpret_cast<float (*)[128][PAD]>(sm1 + 2 * 128 * PAD);

    const int tid  = threadIdx.x;
    const int bn   = blockIdx.x;   // head
    const int bm   = blockIdx.y;
    const int lane = tid & 31;
    const int warp = tid >> 5;
    const int wm   = warp & 3;
    const int wn   = warp >> 2;

    const int lrow = tid >> 3;
    const int lc4  = (tid & 7) * 4;

    const float* xg = x + (size_t)(bm * 128) * D_ + lc4;
    const float* wg = W + (size_t)(bn * 128) * D_ + lc4;

    auto load_tiles = [&](int buf, int kc) {
#pragma unroll
        for (int it = 0; it < 4; it++) {
            int r = lrow + it * 32;
            uint32_t da = (uint32_t)__cvta_generic_to_shared(&As[buf][r][lc4]);
            CP_ASYNC16(da, xg + (size_t)r * D_ + kc);
            uint32_t db = (uint32_t)__cvta_generic_to_shared(&Bs[buf][r][lc4]);
            CP_ASYNC16(db, wg + (size_t)r * D_ + kc);
        }
        asm volatile("cp.async.commit_group;\n" ::: "memory");
    };

    float acc[2][8][4];
#pragma unroll
    for (int mt = 0; mt < 2; mt++)
#pragma unroll
        for (int nt = 0; nt < 8; nt++)
#pragma unroll
            for (int q = 0; q < 4; q++) acc[mt][nt][q] = 0.f;

    load_tiles(0, 0);

    const int r4 = lane >> 2;
    const int c4 = lane & 3;

    for (int kc = 0; kc < D_; kc += KC) {
        int buf = (kc / KC) & 1;
        if (kc + KC < D_) {
            load_tiles(buf ^ 1, kc + KC);
            asm volatile("cp.async.wait_group 1;\n" ::: "memory");
        } else {
            asm volatile("cp.async.wait_group 0;\n" ::: "memory");
        }
        __syncthreads();

#pragma unroll
        for (int kk = 0; kk < KC / 8; kk++) {
            const int k0 = kk * 8;
            uint32_t af[2][4];
            uint32_t bf[8][2];
#pragma unroll
            for (int mt = 0; mt < 2; mt++) {
                const int rb = wm * 32 + mt * 16;
                af[mt][0] = cvt_tf32(As[buf][rb + r4][k0 + c4]);
                af[mt][1] = cvt_tf32(As[buf][rb + r4 + 8][k0 + c4]);
                af[mt][2] = cvt_tf32(As[buf][rb + r4][k0 + c4 + 4]);
                af[mt][3] = cvt_tf32(As[buf][rb + r4 + 8][k0 + c4 + 4]);
            }
#pragma unroll
            for (int nt = 0; nt < 8; nt++) {
                const int nb = wn * 64 + nt * 8 + r4;
                bf[nt][0] = cvt_tf32(Bs[buf][nb][k0 + c4]);
                bf[nt][1] = cvt_tf32(Bs[buf][nb][k0 + c4 + 4]);
            }
#pragma unroll
            for (int mt = 0; mt < 2; mt++)
#pragma unroll
                for (int nt = 0; nt < 8; nt++)
                    mma_tf32(acc[mt][nt], af[mt], bf[nt]);
        }
        __syncthreads();
    }

    // ---------------- fused epilogue ----------------
    float* Es = sm1;   // [128][EST]
    const int c2 = (lane & 3) * 2;
#pragma unroll
    for (int mt = 0; mt < 2; mt++) {
        const int rA = wm * 32 + mt * 16 + r4;
#pragma unroll
        for (int nt = 0; nt < 8; nt++) {
            const int n0 = wn * 64 + nt * 8 + c2;
            Es[rA * EST + n0]           = acc[mt][nt][0];
            Es[rA * EST + n0 + 1]       = acc[mt][nt][1];
            Es[(rA + 8) * EST + n0]     = acc[mt][nt][2];
            Es[(rA + 8) * EST + n0 + 1] = acc[mt][nt][3];
        }
    }
    __syncthreads();

    // si/sj (full fp32 precision)
    {
        const float4 wl4 = reinterpret_cast<const float4*>(attn_w)[lane];
        const float4 wr4 = reinterpret_cast<const float4*>(attn_w + C_)[lane];
#pragma unroll
        for (int rr = 0; rr < 16; rr++) {
            const int r = warp * 16 + rr;
            const float* er = Es + r * EST + lane * 4;
            float a0 = er[0], a1 = er[1], a2 = er[2], a3 = er[3];
            float pj = a0 * wl4.x + a1 * wl4.y + a2 * wl4.z + a3 * wl4.w;
            float pi = a0 * wr4.x + a1 * wr4.y + a2 * wr4.z + a3 * wr4.w;
#pragma unroll
            for (int off = 16; off > 0; off >>= 1) {
                pj += __shfl_xor_sync(0xffffffffu, pj, off);
                pi += __shfl_xor_sync(0xffffffffu, pi, off);
            }
            if (lane == 0) {
                const int mg = bm * 128 + r;
                sj_buf[bn * MTOT + mg] = pj;
                si_buf[bn * MTOT + mg] = pi;
            }
        }
    }

    // transposed write, pre-rounded to tf32 bits
#pragma unroll
    for (int ff = 0; ff < 16; ff++) {
        const int f = warp * 16 + ff;
#pragma unroll
        for (int c = 0; c < 4; c++) {
            const int ml = c * 32 + lane;
            const float v = Es[ml * EST + f];
            const int mg = bm * 128 + ml;
            const int bb = mg / 133;
            const int nn = mg - bb * 133;
            gT_buf[((size_t)(bb * H_ + bn) * C_ + f) * GTS + nn] =
                __uint_as_float(cvt_tf32(v));
        }
    }
}

// =========================================================================
// Kernel 2 (attention): per (b,h), 512 threads
// =========================================================================
#define AKS 17

__global__ __launch_bounds__(512)
void attn_mma_kernel(float* __restrict__ out) {
    extern __shared__ float sm[];
    float* Psh  = sm;                    // [144][PST]
    float* gTs  = Psh + 144 * PST;       // [128][GTS], swizzled tf32 bits
    float* ssi  = gTs + 128 * GTS;       // [144]
    float* ssj  = ssi + 144;
    float* dinv = ssj + 144;

    const int h = blockIdx.x;
    const int b = blockIdx.y;
    const int tid  = threadIdx.x;
    const int lane = tid & 31;
    const int warp = tid >> 5;

    // 1) stage gT slice via cp.async (swizzled on 16B columns)
    {
        const float* gsrc = gT_buf + (size_t)(b * H_ + h) * C_ * GTS;
#pragma unroll
        for (int it = 0; it < 9; it++) {
            const int p = tid + it * 512;
            if (p < 128 * 34) {
                const int f  = p / 34;
                const int j4 = p - f * 34;
                const int sw = (j4 < 32) ? (j4 ^ ((f >> 3) & 7)) : j4;
                uint32_t dst = (uint32_t)__cvta_generic_to_shared(&gTs[f * GTS + sw * 4]);
                CP_ASYNC16(dst, gsrc + f * GTS + j4 * 4);
            }
        }
        asm volatile("cp.async.commit_group;\n" ::: "memory");
    }

    // 2) scores + zero P (float4)
    for (int i = tid; i < 144; i += 512) {
        ssi[i] = (i < N_) ? si_buf[h * MTOT + b * N_ + i] : 0.f;
        ssj[i] = (i < N_) ? sj_buf[h * MTOT + b * N_ + i] : 0.f;
    }
    {
        float4* P4 = reinterpret_cast<float4*>(Psh);
        const float4 z = make_float4(0.f, 0.f, 0.f, 0.f);
        for (int p = tid; p < 144 * PST / 4; p += 512) P4[p] = z;
    }
    const int nnz = nz_cnt;
    __syncthreads();

    // 3) build unnormalized P at nonzeros only
    for (int e = tid; e < nnz; e += 512) {
        const int pk = nz_list[e];
        const int i  = pk >> 8;
        const int j  = pk & 255;
        float v = ssi[i] + ssj[j];
        v = (v > 0.f) ? v : NEG_SLOPE * v;
        Psh[i * PST + j] = __expf(v);
    }
    __syncthreads();

    // 4) column sums (softmax axis = i) -> 1/denom
    for (int j = tid; j < N_; j += 512) {
        float s = 0.f;
#pragma unroll 7
        for (int i = 0; i < N_; i++) s += Psh[i * PST + j];
        dinv[j] = 1.0f / s;
    }
    __syncthreads();

    // 5) fold 1/denom into P at nonzeros, round to tf32 bits
    for (int e = tid; e < nnz; e += 512) {
        const int pk = nz_list[e];
        const int i  = pk >> 8;
        const int j  = pk & 255;
        Psh[i * PST + j] = __uint_as_float(cvt_tf32(Psh[i * PST + j] * dinv[j]));
    }

    asm volatile("cp.async.wait_group 0;\n" ::: "memory");
    __syncthreads();

    // 6) mma: out = P' @ gT^T  (16 warps: wm 0..3 x wn 0..3)
    const int wm = warp & 3;
    const int wn = warp >> 2;
    const int r4 = lane >> 2;
    const int c4 = lane & 3;

    float acc[3][4][4];
#pragma unroll
    for (int mi = 0; mi < 3; mi++)
#pragma unroll
        for (int nt = 0; nt < 4; nt++)
#pragma unroll
            for (int q = 0; q < 4; q++) acc[mi][nt][q] = 0.f;

#pragma unroll
    for (int ks = 0; ks < AKS; ks++) {
        const int ka  = ks * 8 + c4;
        const int kb  = ka + 4;
        const int j4a = 2 * ks;
        const int j4b = 2 * ks + 1;
        uint32_t bf[4][2];
#pragma unroll
        for (int nt = 0; nt < 4; nt++) {
            const int n   = wn * 32 + nt * 8 + r4;
            const int key = (n >> 3) & 7;
            const int sa  = (j4a < 32) ? (j4a ^ key) : j4a;
            const int sb  = (j4b < 32) ? (j4b ^ key) : j4b;
            bf[nt][0] = __float_as_uint(gTs[n * GTS + sa * 4 + (ka & 3)]);
            bf[nt][1] = __float_as_uint(gTs[n * GTS + sb * 4 + (kb & 3)]);
        }
#pragma unroll
        for (int mi = 0; mi < 3; mi++) {
            const int mt = wm + mi * 4;
            if (mt >= 9) break;
            const int m0 = mt * 16;
            uint32_t af[4];
            af[0] = __float_as_uint(Psh[(m0 + r4) * PST + ka]);
            af[1] = __float_as_uint(Psh[(m0 + r4 + 8) * PST + ka]);
            af[2] = __float_as_uint(Psh[(m0 + r4) * PST + kb]);
            af[3] = __float_as_uint(Psh[(m0 + r4 + 8) * PST + kb]);
#pragma unroll
            for (int nt = 0; nt < 4; nt++)
                mma_tf32(acc[mi][nt], af, bf[nt]);
        }
    }

    // 7) epilogue
    const int c2 = c4 * 2;
#pragma unroll
    for (int mi = 0; mi < 3; mi++) {
        const int mt = wm + mi * 4;
        if (mt >= 9) break;
        const int i1 = mt * 16 + r4;
        const int i2 = i1 + 8;
#pragma unroll
        for (int nt = 0; nt < 4; nt++) {
            const int f0 = wn * 32 + nt * 8 + c2;
            if (i1 < N_) {
                float2 v = make_float2(acc[mi][nt][0], acc[mi][nt][1]);
                *reinterpret_cast<float2*>(out + (size_t)(b * N_ + i1) * NOUT + h * C_ + f0) = v;
            }
            if (i2 < N_) {
                float2 v = make_float2(acc[mi][nt][2], acc[mi][nt][3]);
                *reinterpret_cast<float2*>(out + (size_t)(b * N_ + i2) * NOUT + h * C_ + f0) = v;
            }
        }
    }
}

// =========================================================================
// launch
// =========================================================================
extern "C" void kernel_launch(void* const* d_in, const int* in_sizes, int n_in,
                              void* d_out, int out_size) {
    const float* x      = (const float*)d_in[0];
    const float* W      = (const float*)d_in[1];
    const float* attn_w = (const float*)d_in[2];
    const float* adj    = (const float*)d_in[3];
    float* out          = (float*)d_out;

    const int smem1 = 2 * 128 * PAD * 2 * sizeof(float);                     // 73728 B
    const int smem3 = (144 * PST + 128 * GTS + 3 * 144) * sizeof(float);     // ~152 KB

    cudaFuncSetAttribute(gemm1_kernel,    cudaFuncAttributeMaxDynamicSharedMemorySize, smem1);
    cudaFuncSetAttribute(attn_mma_kernel, cudaFuncAttributeMaxDynamicSharedMemorySize, smem3);

    nz_zero_kernel<<<1, 1>>>();
    nz_build_kernel<<<(N_ * N_ + 255) / 256, 256>>>(adj);

    dim3 g1(NOUT / 128, MTOT / 128);
    gemm1_kernel<<<g1, 256, smem1>>>(x, W, attn_w);

    dim3 g3(H_, B_);
    attn_mma_kernel<<<g3, 512, smem3>>>(out);
}